// round 12
// baseline (speedup 1.0000x reference)
#include <cuda_runtime.h>
#include <cuda_fp16.h>
#include <math.h>
#include <stdint.h>

// Problem dims (fixed)
#define BB   8
#define TT   4096
#define DD   512
#define HH   512
#define MM   (BB*TT)          // 32768 rows
#define NN   (2*HH)           // 1024 gemm cols
#define KK   DD               // 512

// Chunked scan config
#define CNK  64
#define CL   (TT/CNK)         // 64
#define NSEQ (BB*HH)          // 4096

// Ticket ranges
#define NT_LN    256                         // 256 ln items (128 rows each)
#define NT_GEMM  2048                        // 256 rowblocks x 8 colblocks
#define NT_SCAN3 512                         // 8 batches x 64 chunks
#define NT_TOTAL (NT_LN + NT_GEMM + NT_SCAN3)
#define GRID_P   296                         // <= 2/SM x 148+; dynamic tickets => any resident count is safe

// ---------------- scratch ----------------
__device__ __align__(16) __half g_xn[(size_t)MM * DD];   // 32 MB
__device__ __align__(16) __half g_Wt[(size_t)NN * KK];   // 1 MB
__device__ __align__(16) __half2 g_cv[(size_t)MM * HH];  // 64 MB packed (c,v)
__device__ float g_A [CNK * NSEQ];
__device__ float g_Bc[CNK * NSEQ];
__device__ float g_P [CNK * NSEQ];
// sync state (re-initialized every call by init_wt_kernel)
__device__ int g_ticket;
__device__ int g_lnflag[NT_LN];
__device__ int g_btc[BB];
__device__ int g_bready[BB];

// ---------------- helpers ----------------
#define CP_ASYNC16(dst, src) \
    asm volatile("cp.async.cg.shared.global [%0], [%1], 16;" :: "r"(dst), "l"(src))
#define CP_COMMIT() asm volatile("cp.async.commit_group;" ::: "memory")
#define CP_WAIT0()  asm volatile("cp.async.wait_group 0;" ::: "memory")
#define CP_WAIT1()  asm volatile("cp.async.wait_group 1;" ::: "memory")

#define MMA_F16(d, a, b) \
    asm volatile("mma.sync.aligned.m16n8k16.row.col.f32.f16.f16.f32 " \
        "{%0,%1,%2,%3}, {%4,%5,%6,%7}, {%8,%9}, {%0,%1,%2,%3};" \
        : "+f"((d)[0]), "+f"((d)[1]), "+f"((d)[2]), "+f"((d)[3]) \
        : "r"((a)[0]), "r"((a)[1]), "r"((a)[2]), "r"((a)[3]), \
          "r"((b)[0]), "r"((b)[1]))

#define LDSM4(R0, R1, R2, R3, addr) \
    asm volatile("ldmatrix.sync.aligned.m8n8.x4.shared.b16 {%0,%1,%2,%3}, [%4];" \
        : "=r"(R0), "=r"(R1), "=r"(R2), "=r"(R3) : "r"(addr))

// ---------------- init + W transpose/interleave ----------------
__global__ void __launch_bounds__(256) init_wt_kernel(const float* __restrict__ W) {
    const int idx = blockIdx.x * 256 + threadIdx.x;   // < NN*KK
    if (blockIdx.x == 0) {
        const int t = threadIdx.x;
        if (t < NT_LN) g_lnflag[t] = 0;
        if (t < BB) { g_btc[t] = NT_GEMM / BB; g_bready[t] = 0; }
        if (t == 0) g_ticket = 0;
    }
    const int np = idx >> 9;
    const int k  = idx & 511;
    const int h  = np >> 1;
    const int gs = np & 1;
    g_Wt[idx] = __float2half_rn(W[(size_t)k * NN + gs * HH + h]);
}

// ---------------- GEMM config ----------------
#define BM 128
#define BN 128
#define BK 64
#define NSTG (KK / BK)           // 8
#define ROWB 144                  // bytes per smem row (72 halves)
#define TILEB (BM * ROWB)         // 18432
#define NBUF 3
#define SMEM_BYTES (2 * NBUF * TILEB)   // 110592

// A rows stored PERMUTED: smem slot p = mi*16 + rr*8 + g holds logical row
//   g*8 + mi*2 + rr  (within each 64-row warp block)
__device__ __forceinline__ void load_stage(const __half* __restrict__ Ag,
                                           const __half* __restrict__ Bg,
                                           uint32_t sA, uint32_t sB,
                                           int k0, int tid) {
    #pragma unroll
    for (int i = 0; i < 4; i++) {                 // A: 128 rows x 64 halves
        int q  = tid + i * 256;
        int ms = q >> 3, k8 = q & 7;
        int srow = (ms & 64) | (((ms & 7) << 3) + (((ms >> 4) & 3) << 1) + ((ms >> 3) & 1));
        CP_ASYNC16(sA + ms * ROWB + k8 * 16,
                   Ag + (size_t)srow * KK + k0 + k8 * 8);
    }
    #pragma unroll
    for (int i = 0; i < 4; i++) {                 // B: 128 rows x 64 halves
        int q = tid + i * 256;
        int n = q >> 3, k8 = q & 7;
        CP_ASYNC16(sB + n * ROWB + k8 * 16,
                   Bg + (size_t)n * KK + k0 + k8 * 8);
    }
}

// ---------------- work item: LayerNorm (128 rows, 2 groups of 128 thr) --------
__device__ void do_ln(int r, const float* __restrict__ x,
                      const float* __restrict__ gamma,
                      const float* __restrict__ beta, int tid) {
    __shared__ float sA_[2][4], sB_[2][4], sMu[2], sRs[2];
    const int g  = tid >> 7;
    const int gt = tid & 127;
    const int w  = gt >> 5;
    const int l  = gt & 31;
    float4 gam = ((const float4*)gamma)[gt];
    float4 bet = ((const float4*)beta)[gt];
    for (int it = 0; it < 64; it++) {
        const int row = r * 128 + it * 2 + g;
        float4 v = ((const float4*)(x + (size_t)row * DD))[gt];
        float s  = v.x + v.y + v.z + v.w;
        float ss = v.x*v.x + v.y*v.y + v.z*v.z + v.w*v.w;
        #pragma unroll
        for (int o = 16; o; o >>= 1) {
            s  += __shfl_xor_sync(0xffffffffu, s,  o);
            ss += __shfl_xor_sync(0xffffffffu, ss, o);
        }
        if (l == 0) { sA_[g][w] = s; sB_[g][w] = ss; }
        __syncthreads();
        if (gt == 0) {
            float S  = sA_[g][0] + sA_[g][1] + sA_[g][2] + sA_[g][3];
            float SS = sB_[g][0] + sB_[g][1] + sB_[g][2] + sB_[g][3];
            float mu  = S * (1.0f / DD);
            float var = SS * (1.0f / DD) - mu * mu;
            sMu[g] = mu;
            sRs[g] = rsqrtf(var + 1e-10f);
        }
        __syncthreads();
        const float mu = sMu[g], rs = sRs[g];
        __half2 o01 = __floats2half2_rn((v.x - mu) * rs * gam.x + bet.x,
                                        (v.y - mu) * rs * gam.y + bet.y);
        __half2 o23 = __floats2half2_rn((v.z - mu) * rs * gam.z + bet.z,
                                        (v.w - mu) * rs * gam.w + bet.w);
        __half2* dst = (__half2*)(g_xn + (size_t)row * DD);
        dst[2 * gt]     = o01;
        dst[2 * gt + 1] = o23;
        __syncthreads();
    }
    __threadfence();
    __syncthreads();
    if (tid == 0) atomicExch(&g_lnflag[r], 1);
}

// ---------------- work item: scan2 for one batch (inline, 256 threads) --------
__device__ void do_scan2(int b, float* __restrict__ hidden, int tid) {
    const int L = tid & 7;
    #pragma unroll 1
    for (int pass = 0; pass < 16; pass++) {
        const int seq = b * HH + pass * 32 + (tid >> 3);
        float a[8], bb[8];
        #pragma unroll
        for (int i = 0; i < 8; i++) {
            a [i] = __ldcg(&g_A [(L * 8 + i) * NSEQ + seq]);
            bb[i] = __ldcg(&g_Bc[(L * 8 + i) * NSEQ + seq]);
        }
        float CA = 1.0f, CB = 0.0f;
        #pragma unroll
        for (int i = 0; i < 8; i++) { CB = fmaf(a[i], CB, bb[i]); CA *= a[i]; }
        #pragma unroll
        for (int d = 1; d < 8; d <<= 1) {
            float pA = __shfl_up_sync(0xffffffffu, CA, d, 8);
            float pB = __shfl_up_sync(0xffffffffu, CB, d, 8);
            if (L >= d) { CB = fmaf(CA, pB, CB); CA *= pA; }
        }
        float pB = __shfl_up_sync(0xffffffffu, CB, 1, 8);
        float p = (L == 0) ? 0.0f : pB;
        #pragma unroll
        for (int i = 0; i < 8; i++) {
            g_P[(L * 8 + i) * NSEQ + seq] = p;
            p = fmaf(a[i], p, bb[i]);
        }
        if (L == 7) hidden[seq] = p;
    }
}

// ---------------- work item: GEMM tile + fused act + chunk scan ---------------
__device__ void do_gemm(int tt, char* sm, float* __restrict__ hidden, int tid) {
    const int lane = tid & 31;
    const int grp  = lane >> 2;
    const int q4   = lane & 3;
    const int wid  = tid >> 5;
    const int wm   = wid & 1;
    const int wn   = wid >> 1;
    const int rb   = tt >> 3;
    const int rowBase = rb * BM;
    const int colBase = (tt & 7) * BN;

    __shared__ int s_last;
    if (tid == 0) {                       // wait for LN of this rowblock
        while (atomicAdd(&g_lnflag[rb], 0) == 0) __nanosleep(64);
    }
    __syncthreads();

    const __half* Ag = g_xn + (size_t)rowBase * KK;
    const __half* Bg = g_Wt + (size_t)colBase * KK;

    uint32_t sbase = (uint32_t)__cvta_generic_to_shared(sm);
    uint32_t sA[NBUF], sB[NBUF];
    #pragma unroll
    for (int i = 0; i < NBUF; i++) {
        sA[i] = sbase + (2 * i) * TILEB;
        sB[i] = sbase + (2 * i + 1) * TILEB;
    }

    uint32_t aoff[4], boff[2];
    #pragma unroll
    for (int mi = 0; mi < 4; mi++)
        aoff[mi] = (wm * 64 + mi * 16 + (lane & 15)) * ROWB + (lane >> 4) * 16;
    #pragma unroll
    for (int p = 0; p < 2; p++)
        boff[p] = (wn * 32 + p * 16 + ((lane >> 4) << 3) + (lane & 7)) * ROWB
                  + (((lane >> 3) & 1) << 4);

    float acc[4][4][4];
    #pragma unroll
    for (int i = 0; i < 4; i++)
        #pragma unroll
        for (int j = 0; j < 4; j++)
            #pragma unroll
            for (int p = 0; p < 4; p++) acc[i][j][p] = 0.0f;

    load_stage(Ag, Bg, sA[0], sB[0], 0, tid);
    CP_COMMIT();
    load_stage(Ag, Bg, sA[1], sB[1], BK, tid);
    CP_COMMIT();

    #pragma unroll 1
    for (int s = 0; s < NSTG; s++) {
        if (s == NSTG - 1) { CP_WAIT0(); } else { CP_WAIT1(); }
        __syncthreads();
        if (s + 2 < NSTG) {
            load_stage(Ag, Bg, sA[(s+2)%NBUF], sB[(s+2)%NBUF], (s + 2) * BK, tid);
            CP_COMMIT();
        }
        const uint32_t Ab = sA[s % NBUF];
        const uint32_t Bb = sB[s % NBUF];
        #pragma unroll
        for (int k16 = 0; k16 < 4; k16++) {
            uint32_t a[4][4], b[4][2];
            #pragma unroll
            for (int mi = 0; mi < 4; mi++)
                LDSM4(a[mi][0], a[mi][1], a[mi][2], a[mi][3],
                      Ab + aoff[mi] + k16 * 32);
            #pragma unroll
            for (int p = 0; p < 2; p++)
                LDSM4(b[2*p][0], b[2*p][1], b[2*p+1][0], b[2*p+1][1],
                      Bb + boff[p] + k16 * 32);
            #pragma unroll
            for (int mi = 0; mi < 4; mi++)
                #pragma unroll
                for (int ni = 0; ni < 4; ni++)
                    MMA_F16(acc[mi][ni], a[mi], b[ni]);
        }
    }

    // Epilogue: acc pairs = (k_gate, h_pre) of one h channel; fused chunk scan.
    const int hBase = (colBase >> 1) + wn * 16;
    const int mWarp = rowBase + wm * 64;
    const int bIdx  = rowBase >> 12;
    const int ci    = ((rowBase & (TT - 1)) >> 6) + wm;
    #pragma unroll
    for (int ni = 0; ni < 4; ni++) {
        const int h = hBase + ni * 4 + q4;
        float GA = 1.0f, GB = 0.0f;
        #pragma unroll
        for (int mi = 0; mi < 4; mi++) {
            #pragma unroll
            for (int rr = 0; rr < 2; rr++) {
                float k  = acc[mi][ni][2 * rr];
                float hp = acc[mi][ni][2 * rr + 1];
                k = fminf(fmaxf(k, -30.0f), 30.0f);
                float ek = __expf(k);
                float c  = 1.0f / (1.0f + ek);       // sigmoid(-k)
                float z  = ek * c;                    // sigmoid(k)
                float g  = (hp >= 0.0f) ? (hp + 0.5f)
                                        : (1.0f / (1.0f + __expf(-hp)));
                float v  = z * g;
                const int m = mWarp + grp * 8 + mi * 2 + rr;
                g_cv[(size_t)m * HH + h] = __floats2half2_rn(c, v);
                GB = fmaf(c, GB, v);
                GA *= c;
            }
        }
        #pragma unroll
        for (int s = 1; s < 8; s <<= 1) {
            float a2 = __shfl_down_sync(0xffffffffu, GA, 4 * s);
            float b2 = __shfl_down_sync(0xffffffffu, GB, 4 * s);
            GB = fmaf(GB, a2, b2);
            GA *= a2;
        }
        if (grp == 0) {
            g_A [ci * NSEQ + bIdx * HH + h] = GA;
            g_Bc[ci * NSEQ + bIdx * HH + h] = GB;
        }
    }

    // batch countdown -> last tile runs scan2 inline, then raises ready flag
    __threadfence();
    __syncthreads();
    if (tid == 0) s_last = (atomicSub(&g_btc[bIdx], 1) == 1);
    __syncthreads();
    if (s_last) {
        do_scan2(bIdx, hidden, tid);
        __threadfence();
        __syncthreads();
        if (tid == 0) atomicExch(&g_bready[bIdx], 1);
    }
}

// ---------------- work item: scan3 for one (batch, chunk) ---------------------
__device__ void do_scan3(int item, const float* __restrict__ x,
                         float* __restrict__ out, int tid) {
    const int b  = item >> 6;
    const int ci = item & 63;
    if (tid == 0) {
        while (atomicAdd(&g_bready[b], 0) == 0) __nanosleep(128);
    }
    __syncthreads();
    const int seq0 = b * HH + 2 * tid;
    float hs0 = __ldcg(&g_P[ci * NSEQ + seq0]);
    float hs1 = __ldcg(&g_P[ci * NSEQ + seq0 + 1]);
    size_t off = ((size_t)(b * TT + ci * CL)) * HH + 2 * tid;
    #pragma unroll 4
    for (int l = 0; l < CL; l++) {
        uint2 cvp = *(const uint2*)(g_cv + off);
        float2 cv0 = __half22float2(*(__half2*)&cvp.x);
        float2 cv1 = __half22float2(*(__half2*)&cvp.y);
        float2 xv = *(const float2*)(x + off);
        hs0 = fmaf(cv0.x, hs0, cv0.y);
        hs1 = fmaf(cv1.x, hs1, cv1.y);
        float2 ov = { hs0 + xv.x, hs1 + xv.y };
        *(float2*)(out + off) = ov;
        off += HH;
    }
}

// ---------------- persistent mega kernel ----------------
__global__ void __launch_bounds__(256, 2) mega_kernel(const float* __restrict__ x,
                                                      const float* __restrict__ gamma,
                                                      const float* __restrict__ beta,
                                                      float* __restrict__ hidden,
                                                      float* __restrict__ out) {
    extern __shared__ char sm[];
    __shared__ int s_ticket;
    const int tid = threadIdx.x;
    for (;;) {
        if (tid == 0) s_ticket = atomicAdd(&g_ticket, 1);
        __syncthreads();
        const int t = s_ticket;
        __syncthreads();
        if (t >= NT_TOTAL) break;
        if (t < NT_LN)                 do_ln(t, x, gamma, beta, tid);
        else if (t < NT_LN + NT_GEMM)  do_gemm(t - NT_LN, sm, hidden, tid);
        else                           do_scan3(t - NT_LN - NT_GEMM, x, out, tid);
        __syncthreads();
    }
}

// ---------------- launch ----------------
extern "C" void kernel_launch(void* const* d_in, const int* in_sizes, int n_in,
                              void* d_out, int out_size) {
    const float* x     = (const float*)d_in[0];
    const float* gamma = (const float*)d_in[1];
    const float* beta  = (const float*)d_in[2];
    const float* W     = (const float*)d_in[3];
    float* out    = (float*)d_out;
    float* hidden = out + (size_t)MM * DD;

    cudaFuncSetAttribute(mega_kernel, cudaFuncAttributeMaxDynamicSharedMemorySize,
                         SMEM_BYTES);

    init_wt_kernel<<<(NN * KK) / 256, 256>>>(W);
    mega_kernel<<<GRID_P, 256, SMEM_BYTES>>>(x, gamma, beta, hidden, out);
}